// round 10
// baseline (speedup 1.0000x reference)
#include <cuda_runtime.h>

// Depthwise 3x3 conv, stride 1, VALID, fp32.
// x: (16, 64, 512, 512), w: (64, 3, 3), out: (16, 64, 510, 510).
//
// R9: occupancy lever saturated (occ 58.6% -> DRAM still 83.4%). Reverted.
// R10 = R7 (330 us best) + L2 prefetch 16 rows ahead of each demand load.
// Prefetches take no register / no scoreboard slot -> DRAM stream decoupled
// from per-warp MLP; demand LDGs become L2 hits. Discriminates latency-limit
// (expect ~88-91% DRAM) vs HBM r/w-turnaround ceiling (expect neutral).

namespace {

constexpr int CH    = 64;
constexpr int H     = 512;
constexpr int W     = 512;
constexpr int OH    = 510;
constexpr int OW    = 510;
constexpr int CHUNK = 30;    // 17 chunks * 30 = 510; multiple of 6
constexpr int TPB   = 128;   // 128 threads * 4 outputs = 512 >= OW

__global__ __launch_bounds__(TPB)
void dwconv3x3_kernel(const float* __restrict__ x,
                      const float* __restrict__ wgt,
                      float* __restrict__ out)
{
    const int plane = blockIdx.y;              // n*CH + c   (slow axis)
    const int c     = plane & (CH - 1);
    const int y0    = blockIdx.x * CHUNK;      // chunk = fast axis -> adjacent
                                               // chunks of a plane co-resident
    const float* __restrict__ in = x + (size_t)plane * (H * W);
    float* __restrict__ op       = out + (size_t)plane * (OH * OW);

    const float* wp = wgt + c * 9;
    const float w00 = __ldg(wp + 0), w01 = __ldg(wp + 1), w02 = __ldg(wp + 2);
    const float w10 = __ldg(wp + 3), w11 = __ldg(wp + 4), w12 = __ldg(wp + 5);
    const float w20 = __ldg(wp + 6), w21 = __ldg(wp + 7), w22 = __ldg(wp + 8);

    const int x0   = threadIdx.x * 4;          // 0, 4, ..., 508
    const int lane = threadIdx.x & 31;
    const int yend = y0 + 31;                  // last row this block loads

    // 6-row ring of 6-column strips; fully unrolled -> all registers.
    float r[6][6];

    // L2 prefetch of this thread's line of row yy. No dst reg, no scoreboard.
    // Only rows the block itself will demand-load (<= yend) -> no traffic
    // inflation; L2 footprint ~16 rows * 2KB * 1480 blocks ~ 47 MB < 126 MB.
    auto pf = [&](int yy) {
        if (yy <= yend)
            asm volatile("prefetch.global.L2 [%0];"
                         :: "l"(in + yy * W + x0));
    };

    // One float4 per row per thread; halo cols 4,5 shuffled from lane+1
    // (its a.x, a.y). Lane 31 (warp boundary) loads its own float2 halo.
    auto load_row = [&](float* d, int y) {
        const float4 a = *reinterpret_cast<const float4*>(in + y * W + x0);
        d[0] = a.x; d[1] = a.y; d[2] = a.z; d[3] = a.w;
        d[4] = __shfl_down_sync(0xffffffffu, a.x, 1);
        d[5] = __shfl_down_sync(0xffffffffu, a.y, 1);
        if (lane == 31) {
            if (x0 + 4 < W) {
                const float2 b = *reinterpret_cast<const float2*>(in + y * W + x0 + 4);
                d[4] = b.x; d[5] = b.y;
            } else {
                d[4] = 0.f; d[5] = 0.f;        // x0 == 508: cols 512/513 unused
            }
        }
    };

    // Output row y from rows a (y), b (y+1), cc (y+2). AL16: row byte offset
    // 2040*y is 16B-aligned iff y even; stage parity == row parity (y0 even).
    // Streaming stores keep L2 clean for input-halo + prefetch residency.
    auto proc = [&](const float* a, const float* b, const float* cc, int y,
                    bool al16) {
        float o[4];
        #pragma unroll
        for (int j = 0; j < 4; ++j) {
            float s;
            s = a[j]      * w00;
            s = fmaf(a[j + 1],  w01, s);
            s = fmaf(a[j + 2],  w02, s);
            s = fmaf(b[j],      w10, s);
            s = fmaf(b[j + 1],  w11, s);
            s = fmaf(b[j + 2],  w12, s);
            s = fmaf(cc[j],     w20, s);
            s = fmaf(cc[j + 1], w21, s);
            s = fmaf(cc[j + 2], w22, s);
            o[j] = s;
        }
        float* orow = op + (size_t)y * OW + x0;
        if (x0 + 4 <= OW) {
            if (al16) {
                __stcs(reinterpret_cast<float4*>(orow),
                       make_float4(o[0], o[1], o[2], o[3]));
            } else {
                __stcs(reinterpret_cast<float2*>(orow),     make_float2(o[0], o[1]));
                __stcs(reinterpret_cast<float2*>(orow) + 1, make_float2(o[2], o[3]));
            }
        } else {                                // x0 == 508: only 508/509 valid
            __stcs(reinterpret_cast<float2*>(orow), make_float2(o[0], o[1]));
        }
    };

    // Prologue: demand-load rows y0..y0+5, then prefetch y0+6..y0+15 so the
    // first main-loop loads are already in flight via the prefetch queue.
    #pragma unroll
    for (int k = 0; k < 6; ++k)
        load_row(r[k], y0 + k);
    #pragma unroll
    for (int k = 6; k < 16; ++k)
        pf(y0 + k);

    int y = y0;
    // Each iter: 6 output rows + demand-load of next 6 rows (consumed 4
    // stages later) + L2 prefetch 16 rows ahead.
    #pragma unroll 1
    for (int i = 0; i < CHUNK / 6 - 1; ++i) {
        proc(r[0], r[1], r[2], y + 0, true ); load_row(r[0], y + 6);  pf(y + 16);
        proc(r[1], r[2], r[3], y + 1, false); load_row(r[1], y + 7);  pf(y + 17);
        proc(r[2], r[3], r[4], y + 2, true ); load_row(r[2], y + 8);  pf(y + 18);
        proc(r[3], r[4], r[5], y + 3, false); load_row(r[3], y + 9);  pf(y + 19);
        proc(r[4], r[5], r[0], y + 4, true ); load_row(r[4], y + 10); pf(y + 20);
        proc(r[5], r[0], r[1], y + 5, false); load_row(r[5], y + 11); pf(y + 21);
        y += 6;
    }

    // Epilogue: only rows y+6, y+7 still needed (stages 4/5).
    // y+7 = y0+31 <= 511 for the last chunk — in bounds, no clamps.
    proc(r[0], r[1], r[2], y + 0, true ); load_row(r[0], y + 6);
    proc(r[1], r[2], r[3], y + 1, false); load_row(r[1], y + 7);
    proc(r[2], r[3], r[4], y + 2, true );
    proc(r[3], r[4], r[5], y + 3, false);
    proc(r[4], r[5], r[0], y + 4, true );
    proc(r[5], r[0], r[1], y + 5, false);
}

} // namespace

extern "C" void kernel_launch(void* const* d_in, const int* in_sizes, int n_in,
                              void* d_out, int out_size)
{
    const float* x = (const float*)d_in[0];
    const float* w = (const float*)d_in[1];
    float* out     = (float*)d_out;

    const int planes = in_sizes[0] / (H * W);   // 16 * 64 = 1024
    dim3 grid(OH / CHUNK, planes);              // (17, 1024) — chunk fastest
    dwconv3x3_kernel<<<grid, TPB>>>(x, w, out);
}

// round 11
// speedup vs baseline: 1.0280x; 1.0280x over previous
#include <cuda_runtime.h>

// Depthwise 3x3 conv, stride 1, VALID, fp32.
// x: (16, 64, 512, 512), w: (64, 3, 3), out: (16, 64, 510, 510).
//
// R8-R10 established: occupancy saturated (>~34 warps/SM buys nothing),
// L2 prefetch neutral-to-negative -> we sit at the HBM mixed read/write
// turnaround ceiling (~84% of 8 TB/s). Prefetch reverted.
// R11 = R7 (330.1 us best) with pointer-increment addressing: one input and
// one output base pointer advanced by 6 rows per iteration; every access is
// a constant-offset LDG/STG (offsets <= 24.5 KB fit the SASS imm field).
// Cuts per-stage IMAD address math roughly in half.

namespace {

constexpr int CH    = 64;
constexpr int H     = 512;
constexpr int W     = 512;
constexpr int OH    = 510;
constexpr int OW    = 510;
constexpr int CHUNK = 30;    // 17 chunks * 30 = 510; multiple of 6
constexpr int TPB   = 128;   // 128 threads * 4 outputs = 512 >= OW

__global__ __launch_bounds__(TPB)
void dwconv3x3_kernel(const float* __restrict__ x,
                      const float* __restrict__ wgt,
                      float* __restrict__ out)
{
    const int plane = blockIdx.y;              // n*CH + c   (slow axis)
    const int c     = plane & (CH - 1);
    const int y0    = blockIdx.x * CHUNK;      // chunk = fast axis -> adjacent
                                               // chunks of a plane co-resident
    const float* wp = wgt + c * 9;
    const float w00 = __ldg(wp + 0), w01 = __ldg(wp + 1), w02 = __ldg(wp + 2);
    const float w10 = __ldg(wp + 3), w11 = __ldg(wp + 4), w12 = __ldg(wp + 5);
    const float w20 = __ldg(wp + 6), w21 = __ldg(wp + 7), w22 = __ldg(wp + 8);

    const int x0   = threadIdx.x * 4;          // 0, 4, ..., 508
    const int lane = threadIdx.x & 31;
    const bool full  = (x0 + 4 <= OW);         // false only for x0 == 508
    const bool halo  = (x0 + 4 < W);           // lane-31 halo load in bounds

    // Base pointers; advanced by 6 rows per iteration so all accesses inside
    // the loop are [reg + constant] (no per-stage address IMADs).
    const float* __restrict__ pin =
        x + (size_t)plane * (H * W) + (size_t)y0 * W + x0;
    float* __restrict__ pout =
        out + (size_t)plane * (OH * OW) + (size_t)y0 * OW + x0;

    // 6-row ring of 6-column strips; fully unrolled -> all registers.
    float r[6][6];

    // Load row (pin + k*W). One float4 per thread; halo cols 4,5 shuffled
    // from lane+1 (its a.x, a.y); lane 31 loads its own float2 halo.
    auto load_row = [&](float* d, const float* p, int k) {
        const float4 a = *reinterpret_cast<const float4*>(p + k * W);
        d[0] = a.x; d[1] = a.y; d[2] = a.z; d[3] = a.w;
        d[4] = __shfl_down_sync(0xffffffffu, a.x, 1);
        d[5] = __shfl_down_sync(0xffffffffu, a.y, 1);
        if (lane == 31) {
            if (halo) {
                const float2 b = *reinterpret_cast<const float2*>(p + k * W + 4);
                d[4] = b.x; d[5] = b.y;
            } else {
                d[4] = 0.f; d[5] = 0.f;        // x0 == 508: cols 512/513 unused
            }
        }
    };

    // Output row (pout + k*OW) from rows a, b, cc. AL16: byte offset of row
    // y is 2040*y + 4*x0 -> 16B-aligned iff y even; stage parity == row
    // parity (y0 even). Streaming stores keep L2 clean for halo reuse.
    auto proc = [&](const float* a, const float* b, const float* cc,
                    float* p, int k, bool al16) {
        float o[4];
        #pragma unroll
        for (int j = 0; j < 4; ++j) {
            float s;
            s = a[j]      * w00;
            s = fmaf(a[j + 1],  w01, s);
            s = fmaf(a[j + 2],  w02, s);
            s = fmaf(b[j],      w10, s);
            s = fmaf(b[j + 1],  w11, s);
            s = fmaf(b[j + 2],  w12, s);
            s = fmaf(cc[j],     w20, s);
            s = fmaf(cc[j + 1], w21, s);
            s = fmaf(cc[j + 2], w22, s);
            o[j] = s;
        }
        float* orow = p + k * OW;
        if (full) {
            if (al16) {
                __stcs(reinterpret_cast<float4*>(orow),
                       make_float4(o[0], o[1], o[2], o[3]));
            } else {
                __stcs(reinterpret_cast<float2*>(orow),     make_float2(o[0], o[1]));
                __stcs(reinterpret_cast<float2*>(orow) + 1, make_float2(o[2], o[3]));
            }
        } else {                                // x0 == 508: only 508/509 valid
            __stcs(reinterpret_cast<float2*>(orow), make_float2(o[0], o[1]));
        }
    };

    // Prologue: rows y0 .. y0+5 (y0 <= 480 -> max row 485, in bounds).
    #pragma unroll
    for (int k = 0; k < 6; ++k)
        load_row(r[k], pin, k);

    // Each iter: 6 output rows + demand-load of the next 6 input rows
    // (load at stage k consumed 4 stages later).
    #pragma unroll 1
    for (int i = 0; i < CHUNK / 6 - 1; ++i) {
        proc(r[0], r[1], r[2], pout, 0, true ); load_row(r[0], pin, 6);
        proc(r[1], r[2], r[3], pout, 1, false); load_row(r[1], pin, 7);
        proc(r[2], r[3], r[4], pout, 2, true ); load_row(r[2], pin, 8);
        proc(r[3], r[4], r[5], pout, 3, false); load_row(r[3], pin, 9);
        proc(r[4], r[5], r[0], pout, 4, true ); load_row(r[4], pin, 10);
        proc(r[5], r[0], r[1], pout, 5, false); load_row(r[5], pin, 11);
        pin  += 6 * W;
        pout += 6 * OW;
    }

    // Epilogue: only rows +6, +7 still needed (consumed at stages 4/5).
    // Last chunk: y0+31 = 511 — in bounds, no clamps.
    proc(r[0], r[1], r[2], pout, 0, true ); load_row(r[0], pin, 6);
    proc(r[1], r[2], r[3], pout, 1, false); load_row(r[1], pin, 7);
    proc(r[2], r[3], r[4], pout, 2, true );
    proc(r[3], r[4], r[5], pout, 3, false);
    proc(r[4], r[5], r[0], pout, 4, true );
    proc(r[5], r[0], r[1], pout, 5, false);
}

} // namespace

extern "C" void kernel_launch(void* const* d_in, const int* in_sizes, int n_in,
                              void* d_out, int out_size)
{
    const float* x = (const float*)d_in[0];
    const float* w = (const float*)d_in[1];
    float* out     = (float*)d_out;

    const int planes = in_sizes[0] / (H * W);   // 16 * 64 = 1024
    dim3 grid(OH / CHUNK, planes);              // (17, 1024) — chunk fastest
    dwconv3x3_kernel<<<grid, TPB>>>(x, w, out);
}